// round 8
// baseline (speedup 1.0000x reference)
#include <cuda_runtime.h>

// SurfEval: NURBS surface evaluation. B=8, M=N=64, P=Q=3, GRID=512, DIM=3.
// Inputs: ctrl_pts [B,M,N,4], uspan [G], vspan [G], Nu [G,4], Nv [G,4]
// Output: float32 [B, G, G, 3]
//
// R4 design (resubmit #4; broker timeouts in R4-R7):
//   MUFU pipe is the theorized floor (1 RCP/point, rt=8cyc/SMSP -> 15.7us).
//   Batch 4 reciprocals into 1 rcp.approx + Newton (FMA pipe).
//   256 thr/CTA, 2 rows/CTA, 4 pts/thread, launch_bounds(256,5) for occupancy.

#define BB    8
#define MM    64
#define NN    64
#define GRIDD 512
#define RPC   2          // rows (g values) per CTA
#define PPT   4          // points (h values) per thread

__global__ __launch_bounds__(256, 5)
void surf_eval_kernel(const float* __restrict__ ctrl,
                      const int*   __restrict__ uspan,
                      const int*   __restrict__ vspan,
                      const float* __restrict__ Nu,
                      const float* __restrict__ Nv,
                      float*       __restrict__ out)
{
    __shared__ float su_s[RPC * NN * 4];   // 2 rows of Su[n][d], 2 KB

    const int g0 = blockIdx.x * RPC;       // first u row of this CTA
    const int b  = blockIdx.y;
    const int t  = threadIdx.x;            // 0..255

    // ---- Hoisted Phase-2 operands (overlap latency with Phase 1) ----
    const int irow = t >> 7;               // 0..1: which row
    const int i    = t & 127;              // lane within row
    const int h0   = i * PPT;              // first h of this thread

    const int4 sv4 = *reinterpret_cast<const int4*>(vspan + h0);
    float4 nv[PPT];
    #pragma unroll
    for (int p = 0; p < PPT; p++)
        nv[p] = *reinterpret_cast<const float4*>(Nv + 4 * (h0 + p));

    // ---- Phase 1: u-contraction for 2 rows into shared memory ----
    #pragma unroll
    for (int k = t; k < RPC * NN * 4; k += 256) {
        const int row = k >> 8;            // 0..1
        const int j   = k & 255;           // flattened (n,d)
        const int    su = uspan[g0 + row];
        const float4 nu = *reinterpret_cast<const float4*>(Nu + 4 * (g0 + row));
        const float* base = ctrl + ((size_t)b * MM + (su - 3)) * (NN * 4);
        su_s[k] = nu.x * base[j]
                + nu.y * base[j + 1 * NN * 4]
                + nu.z * base[j + 2 * NN * 4]
                + nu.w * base[j + 3 * NN * 4];
    }
    __syncthreads();

    // ---- Phase 2: v-contraction, 4 consecutive points per thread ----
    const float* su_row = su_s + irow * (NN * 4);
    const int svv[PPT] = { sv4.x, sv4.y, sv4.z, sv4.w };

    float xr[PPT], yr[PPT], zr[PPT], wr[PPT];
    #pragma unroll
    for (int p = 0; p < PPT; p++) {
        const int sv = svv[p];
        const float4 p0 = *reinterpret_cast<const float4*>(su_row + 4 * (sv - 3));
        const float4 p1 = *reinterpret_cast<const float4*>(su_row + 4 * (sv - 2));
        const float4 p2 = *reinterpret_cast<const float4*>(su_row + 4 * (sv - 1));
        const float4 p3 = *reinterpret_cast<const float4*>(su_row + 4 * (sv - 0));
        const float4 c  = nv[p];

        xr[p] = c.x * p0.x + c.y * p1.x + c.z * p2.x + c.w * p3.x;
        yr[p] = c.x * p0.y + c.y * p1.y + c.z * p2.y + c.w * p3.y;
        zr[p] = c.x * p0.z + c.y * p1.z + c.z * p2.z + c.w * p3.z;
        wr[p] = c.x * p0.w + c.y * p1.w + c.z * p2.w + c.w * p3.w;
    }

    // ---- Batched reciprocal: 1 MUFU.RCP per 4 points (was 4) ----
    const float P01 = wr[0] * wr[1];
    const float P23 = wr[2] * wr[3];
    const float P   = P01 * P23;
    float r;
    asm("rcp.approx.f32 %0, %1;" : "=f"(r) : "f"(P));
    r = r * (2.0f - P * r);                // one Newton step on FMA pipe

    float inv[PPT];
    inv[0] = r * wr[1] * P23;
    inv[1] = r * wr[0] * P23;
    inv[2] = r * P01 * wr[3];
    inv[3] = r * P01 * wr[2];

    #pragma unroll
    for (int p = 0; p < PPT; p++) {
        xr[p] *= inv[p];  yr[p] *= inv[p];  zr[p] *= inv[p];
    }

    // ---- Direct coalesced stores: 4 points x 3 floats = 3 float4 ----
    float* orow = out + (((size_t)b * GRIDD + (g0 + irow)) * GRIDD + h0) * 3;
    reinterpret_cast<float4*>(orow)[0] = make_float4(xr[0], yr[0], zr[0], xr[1]);
    reinterpret_cast<float4*>(orow)[1] = make_float4(yr[1], zr[1], xr[2], yr[2]);
    reinterpret_cast<float4*>(orow)[2] = make_float4(zr[2], xr[3], yr[3], zr[3]);
}

extern "C" void kernel_launch(void* const* d_in, const int* in_sizes, int n_in,
                              void* d_out, int out_size)
{
    const float* ctrl  = (const float*)d_in[0];
    const int*   uspan = (const int*)  d_in[1];
    const int*   vspan = (const int*)  d_in[2];
    const float* Nu    = (const float*)d_in[3];
    const float* Nv    = (const float*)d_in[4];
    float*       out   = (float*)d_out;

    dim3 grid(GRIDD / RPC, BB);   // 256 x 8 = 2048 CTAs
    surf_eval_kernel<<<grid, 256>>>(ctrl, uspan, vspan, Nu, Nv, out);
}

// round 10
// speedup vs baseline: 1.6815x; 1.6815x over previous
#include <cuda_runtime.h>

// SurfEval: NURBS surface evaluation. B=8, M=N=64, P=Q=3, GRID=512, DIM=3.
// Inputs: ctrl_pts [B,M,N,4], uspan [G], vspan [G], Nu [G,4], Nv [G,4]
// Output: float32 [B, G, G, 3]
//
// R9 design (resubmit; broker timeout):
//     R8 falsified the MUFU-only theory (rcp/4 but 60% slower; L1-busy doubled).
//     Limiter = LDS unique-address traffic. Fix: interleaved PPT mapping
//     (thread i -> h = i, i+128, i+256, i+384) so each LDS has warp lanes on
//     32 CONSECUTIVE h (R2's broadcast pattern), while keeping batched rcp
//     (MUFU/4) and 4-way ILP. Staged contiguous flush (CTA rows contiguous).

#define BB    8
#define MM    64
#define NN    64
#define GRIDD 512
#define RPC   4          // rows (g values) per CTA
#define PPT   4          // points per thread, stride 128

__global__ __launch_bounds__(512)
void surf_eval_kernel(const float* __restrict__ ctrl,
                      const int*   __restrict__ uspan,
                      const int*   __restrict__ vspan,
                      const float* __restrict__ Nu,
                      const float* __restrict__ Nv,
                      float*       __restrict__ out)
{
    __shared__ float su_s[RPC * NN * 4];        // 4 KB: Su for 4 rows
    __shared__ float row_s[RPC * GRIDD * 3];    // 24 KB: staged output rows

    const int g0 = blockIdx.x * RPC;
    const int b  = blockIdx.y;
    const int t  = threadIdx.x;                 // 0..511

    const int irow = t >> 7;                    // 0..3: which row
    const int i    = t & 127;                   // lane-group index within row

    // ---- Hoisted Phase-2 operands (latency overlaps Phase 1) ----
    int    sv[PPT];
    float4 nv[PPT];
    #pragma unroll
    for (int p = 0; p < PPT; p++) {
        const int h = i + 128 * p;              // interleaved: lanes consecutive
        sv[p] = vspan[h];
        nv[p] = *reinterpret_cast<const float4*>(Nv + 4 * h);
    }

    // ---- Phase 1: u-contraction for 4 rows into shared memory ----
    #pragma unroll
    for (int k = t; k < RPC * NN * 4; k += 512) {
        const int row = k >> 8;                 // 0..3
        const int j   = k & 255;                // flattened (n,d)
        const int    su = uspan[g0 + row];
        const float4 nu = *reinterpret_cast<const float4*>(Nu + 4 * (g0 + row));
        const float* base = ctrl + ((size_t)b * MM + (su - 3)) * (NN * 4);
        su_s[k] = nu.x * base[j]
                + nu.y * base[j + 1 * NN * 4]
                + nu.z * base[j + 2 * NN * 4]
                + nu.w * base[j + 3 * NN * 4];
    }
    __syncthreads();

    // ---- Phase 2: v-contraction, 4 interleaved points per thread ----
    const float* su_row = su_s + irow * (NN * 4);

    float xr[PPT], yr[PPT], zr[PPT], wr[PPT];
    #pragma unroll
    for (int p = 0; p < PPT; p++) {
        const int s = sv[p];
        const float4 p0 = *reinterpret_cast<const float4*>(su_row + 4 * (s - 3));
        const float4 p1 = *reinterpret_cast<const float4*>(su_row + 4 * (s - 2));
        const float4 p2 = *reinterpret_cast<const float4*>(su_row + 4 * (s - 1));
        const float4 p3 = *reinterpret_cast<const float4*>(su_row + 4 * (s - 0));
        const float4 c  = nv[p];

        xr[p] = c.x * p0.x + c.y * p1.x + c.z * p2.x + c.w * p3.x;
        yr[p] = c.x * p0.y + c.y * p1.y + c.z * p2.y + c.w * p3.y;
        zr[p] = c.x * p0.z + c.y * p1.z + c.z * p2.z + c.w * p3.z;
        wr[p] = c.x * p0.w + c.y * p1.w + c.z * p2.w + c.w * p3.w;
    }

    // ---- Batched reciprocal: 1 MUFU.RCP per 4 points ----
    const float P01 = wr[0] * wr[1];
    const float P23 = wr[2] * wr[3];
    const float P   = P01 * P23;
    float r;
    asm("rcp.approx.f32 %0, %1;" : "=f"(r) : "f"(P));
    r = r * (2.0f - P * r);                     // Newton step on FMA pipe

    float inv[PPT];
    inv[0] = r * wr[1] * P23;
    inv[1] = r * wr[0] * P23;
    inv[2] = r * P01 * wr[3];
    inv[3] = r * P01 * wr[2];

    // ---- Stage results (stride-3 smem writes: conflict-free) ----
    float* rs = row_s + irow * (GRIDD * 3);
    #pragma unroll
    for (int p = 0; p < PPT; p++) {
        const int h = i + 128 * p;
        rs[h * 3 + 0] = xr[p] * inv[p];
        rs[h * 3 + 1] = yr[p] * inv[p];
        rs[h * 3 + 2] = zr[p] * inv[p];
    }
    __syncthreads();

    // ---- Phase 3: linear coalesced flush ----
    // CTA's 4 rows are contiguous in out: 4*512*3 = 6144 floats = 1536 float4.
    float4*       dst = reinterpret_cast<float4*>(
        out + ((size_t)b * GRIDD + g0) * GRIDD * 3);
    const float4* src = reinterpret_cast<const float4*>(row_s);
    #pragma unroll
    for (int k = t; k < RPC * GRIDD * 3 / 4; k += 512)
        dst[k] = src[k];
}

extern "C" void kernel_launch(void* const* d_in, const int* in_sizes, int n_in,
                              void* d_out, int out_size)
{
    const float* ctrl  = (const float*)d_in[0];
    const int*   uspan = (const int*)  d_in[1];
    const int*   vspan = (const int*)  d_in[2];
    const float* Nu    = (const float*)d_in[3];
    const float* Nv    = (const float*)d_in[4];
    float*       out   = (float*)d_out;

    dim3 grid(GRIDD / RPC, BB);   // 128 x 8 = 1024 CTAs
    surf_eval_kernel<<<grid, 512>>>(ctrl, uspan, vspan, Nu, Nv, out);
}